// round 6
// baseline (speedup 1.0000x reference)
#include <cuda_runtime.h>
#include <cuda_bf16.h>

// GlobalContextBlock (GCNet), fully fused persistent kernel, v2.
// Shapes fixed: B=32, H=W=64 (HW=4096), C=256, HEADS=8, c1=32, planes=64.
//
// Round-5 ncu: fusion + reverse self-re-read cut DRAM traffic 384->~295MB,
// but occ=23.9% (one 16-warp CTA/SM) left DRAM at 51.7%. v2 keeps the same
// traffic structure with 1024 threads/block (32 warps/SM, occ 50%).
//
// grid = B*4 = 128 blocks x 1024 threads, co-resident; 2 spin grid-barriers
// (generation counters, graph-replay safe).
//   phase 1: each warp owns a contiguous 32-position x 256-ch superchunk:
//            softmax-pooling partials (exp w/o max-sub: |logit| < ~7).
//   mlp:     blocks 0..B-1: reduce partials -> ctx -> MLP -> g_term.
//   phase 2: each warp re-walks ITS OWN superchunk in REVERSE (L1 kept within
//            a launch; L2 holds ~all of x at the barrier) doing out = x+term.

#define HW     4096
#define C      256
#define HEADS  8
#define PLANES 64
#define WPB    32                       // warps per block
#define THREADS (WPB * 32)              // 1024
#define SC_PER_BATCH 128                // warp superchunks per batch
#define SC_POS (HW / SC_PER_BATCH)      // 32 positions per superchunk
#define MAXB   64

__device__ float    g_pnum2[MAXB * SC_PER_BATCH * C];      // [gw][256]
__device__ float    g_pden2[MAXB * SC_PER_BATCH * HEADS];  // [gw][8]
__device__ float    g_term[MAXB * C];
__device__ unsigned g_cnt[2];
__device__ unsigned g_gen[2];

__device__ __forceinline__ void grid_barrier(int k, int nblocks)
{
    __threadfence();
    __syncthreads();
    if (threadIdx.x == 0) {
        const unsigned g = atomicAdd(&g_gen[k], 0u);
        if (atomicAdd(&g_cnt[k], 1u) == (unsigned)nblocks - 1u) {
            g_cnt[k] = 0;
            __threadfence();
            atomicAdd(&g_gen[k], 1u);
        } else {
            while (atomicAdd(&g_gen[k], 0u) == g) __nanosleep(64);
        }
    }
    __syncthreads();
}

__global__ __launch_bounds__(THREADS, 1) void gc_fused_kernel(
    const float* __restrict__ x,  const float* __restrict__ wm,
    const float* __restrict__ bmp,
    const float* __restrict__ w1, const float* __restrict__ b1,
    const float* __restrict__ gamma, const float* __restrict__ beta,
    const float* __restrict__ w2, const float* __restrict__ b2,
    float* __restrict__ out, int B, int nblocks)
{
    const int tid = threadIdx.x;
    const int wid = tid >> 5;
    const int l   = tid & 31;

    // warp's superchunk: gw in [0, B*128)
    const int gw = blockIdx.x * WPB + wid;
    const int b  = gw / SC_PER_BATCH;
    const int s0 = (gw % SC_PER_BATCH) * SC_POS;

    __shared__ float s_ctx[C];
    __shared__ float s_y[PLANES];
    __shared__ float s_stats[2];

    // =======================  Phase 1: pooling partials  ====================
    // Lane l covers channels 4l..4l+3 (half 0) and 128+4l..+3 (half 1).
    // 8-lane group j -> head j (half0) / head 4+j (half1); wm idx = 4*(l&7).
    {
        const float4 wmv = *reinterpret_cast<const float4*>(wm + 4 * (l & 7));
        const float  bm  = bmp[0];
        const float* base = x + ((size_t)b * HW + s0) * C + 4 * l;

        float4 acc0 = make_float4(0.f, 0.f, 0.f, 0.f);
        float4 acc1 = make_float4(0.f, 0.f, 0.f, 0.f);
        float  den0 = 0.f, den1 = 0.f;

        // 16 iterations x 2 positions; 4 float4 loads in flight per iter.
        #pragma unroll 4
        for (int it = 0; it < SC_POS / 2; it++) {
            float4 xv0[2], xv1[2];
            #pragma unroll
            for (int i = 0; i < 2; i++) {
                const float* p = base + (size_t)(it * 2 + i) * C;
                xv0[i] = *reinterpret_cast<const float4*>(p);
                xv1[i] = *reinterpret_cast<const float4*>(p + 128);
            }
            float lg[4];
            #pragma unroll
            for (int i = 0; i < 2; i++) {
                lg[i]     = xv0[i].x*wmv.x + xv0[i].y*wmv.y + xv0[i].z*wmv.z + xv0[i].w*wmv.w;
                lg[2 + i] = xv1[i].x*wmv.x + xv1[i].y*wmv.y + xv1[i].z*wmv.z + xv1[i].w*wmv.w;
            }
            #pragma unroll
            for (int u = 0; u < 4; u++) lg[u] += __shfl_xor_sync(0xFFFFFFFFu, lg[u], 1);
            #pragma unroll
            for (int u = 0; u < 4; u++) lg[u] += __shfl_xor_sync(0xFFFFFFFFu, lg[u], 2);
            #pragma unroll
            for (int u = 0; u < 4; u++) lg[u] += __shfl_xor_sync(0xFFFFFFFFu, lg[u], 4);

            float e[4];
            #pragma unroll
            for (int u = 0; u < 4; u++) e[u] = __expf(lg[u] + bm);

            #pragma unroll
            for (int i = 0; i < 2; i++) {
                acc0.x = fmaf(e[i], xv0[i].x, acc0.x);
                acc0.y = fmaf(e[i], xv0[i].y, acc0.y);
                acc0.z = fmaf(e[i], xv0[i].z, acc0.z);
                acc0.w = fmaf(e[i], xv0[i].w, acc0.w);
                den0  += e[i];
                acc1.x = fmaf(e[2+i], xv1[i].x, acc1.x);
                acc1.y = fmaf(e[2+i], xv1[i].y, acc1.y);
                acc1.z = fmaf(e[2+i], xv1[i].z, acc1.z);
                acc1.w = fmaf(e[2+i], xv1[i].w, acc1.w);
                den1  += e[2+i];
            }
        }

        float* pn = g_pnum2 + (size_t)gw * C;
        *reinterpret_cast<float4*>(pn + 4 * l)       = acc0;
        *reinterpret_cast<float4*>(pn + 128 + 4 * l) = acc1;
        if ((l & 7) == 0) {
            g_pden2[gw * HEADS + (l >> 3)]     = den0;   // heads 0..3
            g_pden2[gw * HEADS + 4 + (l >> 3)] = den1;   // heads 4..7
        }
    }

    grid_barrier(0, nblocks);

    // =======================  MLP (blocks 0..B-1)  ==========================
    if (blockIdx.x < B) {
        const int bb = blockIdx.x;
        if (tid < C) {
            const int c = tid, head = c >> 5;
            float num = 0.f, den = 0.f;
            #pragma unroll 8
            for (int k = 0; k < SC_PER_BATCH; k++) {
                num += g_pnum2[(size_t)(bb * SC_PER_BATCH + k) * C + c];
                den += g_pden2[(bb * SC_PER_BATCH + k) * HEADS + head];
            }
            s_ctx[c] = num / den;
        }
        __syncthreads();

        if (tid < C) {                     // y = ctx @ w1 + b1
            const int p = tid >> 2, q = tid & 3;
            float acc = 0.f;
            #pragma unroll 8
            for (int i = 0; i < 64; i++) {
                const int c = q * 64 + i;
                acc = fmaf(s_ctx[c], w1[c * PLANES + p], acc);
            }
            acc += __shfl_xor_sync(0xFFFFFFFFu, acc, 1);
            acc += __shfl_xor_sync(0xFFFFFFFFu, acc, 2);
            if (q == 0) s_y[p] = acc + b1[p];
        }
        __syncthreads();

        if (tid < 32) {                    // LN stats over 64 planes
            const float v1 = s_y[tid], v2 = s_y[tid + 32];
            float s = v1 + v2, sq = v1 * v1 + v2 * v2;
            #pragma unroll
            for (int m = 16; m > 0; m >>= 1) {
                s  += __shfl_xor_sync(0xFFFFFFFFu, s,  m);
                sq += __shfl_xor_sync(0xFFFFFFFFu, sq, m);
            }
            if (tid == 0) {
                const float mean = s / 64.f;
                const float var  = sq / 64.f - mean * mean;
                s_stats[0] = mean;
                s_stats[1] = rsqrtf(var + 1e-3f);
            }
        }
        __syncthreads();

        if (tid < PLANES) {                // normalize + relu
            const float v = (s_y[tid] - s_stats[0]) * s_stats[1] * gamma[tid] + beta[tid];
            s_y[tid] = fmaxf(v, 0.f);
        }
        __syncthreads();

        if (tid < C) {                     // term = y @ w2 + b2
            const int c = tid;
            float acc = b2[c];
            #pragma unroll 8
            for (int p = 0; p < PLANES; p++)
                acc = fmaf(s_y[p], w2[p * C + c], acc);
            g_term[bb * C + c] = acc;
        }
    }

    grid_barrier(1, nblocks);

    // ==========  Phase 2: out = x + term, reverse walk of own chunk  ========
    {
        const float4 tv0 = *reinterpret_cast<const float4*>(g_term + b * C + 4 * l);
        const float4 tv1 = *reinterpret_cast<const float4*>(g_term + b * C + 128 + 4 * l);
        const float* xb = x   + ((size_t)b * HW + s0) * C + 4 * l;
        float*       ob = out + ((size_t)b * HW + s0) * C + 4 * l;

        #pragma unroll 4
        for (int it = SC_POS / 2 - 1; it >= 0; it--) {
            float4 v0[2], v1[2];
            #pragma unroll
            for (int i = 0; i < 2; i++) {
                const float* p = xb + (size_t)(it * 2 + i) * C;
                v0[i] = *reinterpret_cast<const float4*>(p);
                v1[i] = *reinterpret_cast<const float4*>(p + 128);
            }
            #pragma unroll
            for (int i = 0; i < 2; i++) {
                float* q = ob + (size_t)(it * 2 + i) * C;
                float4 a = v0[i];
                a.x += tv0.x; a.y += tv0.y; a.z += tv0.z; a.w += tv0.w;
                __stcs(reinterpret_cast<float4*>(q), a);
                float4 c2 = v1[i];
                c2.x += tv1.x; c2.y += tv1.y; c2.z += tv1.z; c2.w += tv1.w;
                __stcs(reinterpret_cast<float4*>(q + 128), c2);
            }
        }
    }
}

extern "C" void kernel_launch(void* const* d_in, const int* in_sizes, int n_in,
                              void* d_out, int out_size)
{
    const float* x     = (const float*)d_in[0];
    const float* wm    = (const float*)d_in[1];
    const float* bm    = (const float*)d_in[2];
    const float* w1    = (const float*)d_in[3];
    const float* b1    = (const float*)d_in[4];
    const float* gamma = (const float*)d_in[5];
    const float* beta  = (const float*)d_in[6];
    const float* w2    = (const float*)d_in[7];
    const float* b2    = (const float*)d_in[8];
    float* out = (float*)d_out;

    const int B = in_sizes[0] / (HW * C);   // 32
    const int nblocks = B * 4;              // 128 <= 148 SMs -> co-resident

    gc_fused_kernel<<<nblocks, THREADS>>>(x, wm, bm, w1, b1, gamma, beta,
                                          w2, b2, out, B, nblocks);
}

// round 7
// speedup vs baseline: 1.0516x; 1.0516x over previous
#include <cuda_runtime.h>
#include <cuda_bf16.h>

// GlobalContextBlock (GCNet) — 3-kernel implementation (best structure; the
// persistent-fused variant lost to barrier straggler serialization).
// Shapes fixed: B=32, H=W=64 (HW=4096), C=256, HEADS=8, c1=32, planes=64.
//
// k1: one streaming pass over x: per (batch, head) den = sum exp(logit),
//     num[c] = sum exp(logit)*x  (safe without max-subtraction: |logit|<~7)
// k2: per batch: ctx = num/den; MLP(256->64, LN eps=1e-3, ReLU, 64->256) -> term
// k3: out = x + term[b][c]  (streaming, 8x float4 per thread, 128-reg budget
//     so all 8 loads are genuinely in flight; no bounds predicates)

#define HW    4096
#define C     256
#define C4    64
#define HEADS 8
#define PLANES 64
#define NCHUNK 32                      // spatial chunks per batch in k1
#define POS_PER_CHUNK (HW / NCHUNK)    // 128
#define MAXB  64

__device__ float g_pnum[MAXB * NCHUNK * C];
__device__ float g_pden[MAXB * NCHUNK * HEADS];
__device__ float g_term[MAXB * C];

// ---------------------------------------------------------------------------
// Kernel 1: softmax-weighted spatial pooling partials (single read of x).
// grid = B*NCHUNK, 256 threads (8 warps). Warp w: half=w&1 -> 128 channels;
// positions s0 + (w>>1) + 4k. Lane l owns channels half*128+4l..4l+3.
// UB=8 positions batched; __launch_bounds__(256,3) keeps loads in flight.
// ---------------------------------------------------------------------------
#define UB 8
__global__ __launch_bounds__(256, 3) void gc_pool_kernel(
    const float* __restrict__ x, const float* __restrict__ wm,
    const float* __restrict__ bmp)
{
    const int blk   = blockIdx.x;
    const int b     = blk / NCHUNK;
    const int chunk = blk % NCHUNK;
    const int s0    = chunk * POS_PER_CHUNK;

    const int tid  = threadIdx.x;
    const int w    = tid >> 5;
    const int l    = tid & 31;
    const int half = w & 1;
    const int wrow = w >> 1;            // 0..3

    const float4 wmv = *reinterpret_cast<const float4*>(wm + 4 * (l & 7));
    const float  bm  = bmp[0];

    const float* base = x + ((size_t)b * HW + s0 + wrow) * C + half * 128 + 4 * l;

    float4 acc = make_float4(0.f, 0.f, 0.f, 0.f);
    float  den = 0.f;

    #pragma unroll
    for (int kk = 0; kk < POS_PER_CHUNK / 4 / UB; kk++) {
        float4 xv[UB];
        #pragma unroll
        for (int u = 0; u < UB; u++)
            xv[u] = *reinterpret_cast<const float4*>(
                base + (size_t)(kk * UB + u) * 4 * C);

        float p[UB];
        #pragma unroll
        for (int u = 0; u < UB; u++)
            p[u] = xv[u].x * wmv.x + xv[u].y * wmv.y +
                   xv[u].z * wmv.z + xv[u].w * wmv.w;

        #pragma unroll
        for (int u = 0; u < UB; u++) p[u] += __shfl_xor_sync(0xFFFFFFFFu, p[u], 1);
        #pragma unroll
        for (int u = 0; u < UB; u++) p[u] += __shfl_xor_sync(0xFFFFFFFFu, p[u], 2);
        #pragma unroll
        for (int u = 0; u < UB; u++) p[u] += __shfl_xor_sync(0xFFFFFFFFu, p[u], 4);

        float e[UB];
        #pragma unroll
        for (int u = 0; u < UB; u++) e[u] = __expf(p[u] + bm);

        #pragma unroll
        for (int u = 0; u < UB; u++) {
            acc.x = fmaf(e[u], xv[u].x, acc.x);
            acc.y = fmaf(e[u], xv[u].y, acc.y);
            acc.z = fmaf(e[u], xv[u].z, acc.z);
            acc.w = fmaf(e[u], xv[u].w, acc.w);
            den  += e[u];
        }
    }

    __shared__ float s_num[8][128];
    __shared__ float s_den[8][4];
    s_num[w][4 * l + 0] = acc.x;
    s_num[w][4 * l + 1] = acc.y;
    s_num[w][4 * l + 2] = acc.z;
    s_num[w][4 * l + 3] = acc.w;
    if ((l & 7) == 0) s_den[w][l >> 3] = den;
    __syncthreads();

    {
        const int ch = tid;            // 0..255
        const int hf = ch >> 7;
        const int cl = ch & 127;
        g_pnum[(size_t)blk * C + ch] =
            s_num[hf][cl] + s_num[hf + 2][cl] + s_num[hf + 4][cl] + s_num[hf + 6][cl];
    }
    if (tid < HEADS) {
        const int hf = tid >> 2;
        const int hh = tid & 3;
        g_pden[(size_t)blk * HEADS + tid] =
            s_den[hf][hh] + s_den[hf + 2][hh] + s_den[hf + 4][hh] + s_den[hf + 6][hh];
    }
}

// ---------------------------------------------------------------------------
// Kernel 2: per-batch ctx + bottleneck MLP. grid = B, 256 threads.
// ---------------------------------------------------------------------------
__global__ __launch_bounds__(256) void gc_mlp_kernel(
    const float* __restrict__ w1, const float* __restrict__ b1,
    const float* __restrict__ gamma, const float* __restrict__ beta,
    const float* __restrict__ w2, const float* __restrict__ b2)
{
    const int b   = blockIdx.x;
    const int tid = threadIdx.x;

    __shared__ float s_ctx[C];
    __shared__ float s_y[PLANES];
    __shared__ float s_stats[2];

    {
        const int c = tid;
        const int head = c >> 5;
        float num = 0.f, den = 0.f;
        #pragma unroll
        for (int ch = 0; ch < NCHUNK; ch++) {
            num += g_pnum[((size_t)b * NCHUNK + ch) * C + c];
            den += g_pden[((size_t)b * NCHUNK + ch) * HEADS + head];
        }
        s_ctx[c] = num / den;
    }
    __syncthreads();

    {
        const int p = tid >> 2;
        const int q = tid & 3;
        float acc = 0.f;
        #pragma unroll 8
        for (int i = 0; i < 64; i++) {
            const int c = q * 64 + i;
            acc = fmaf(s_ctx[c], w1[c * PLANES + p], acc);
        }
        acc += __shfl_xor_sync(0xFFFFFFFFu, acc, 1);
        acc += __shfl_xor_sync(0xFFFFFFFFu, acc, 2);
        if (q == 0) s_y[p] = acc + b1[p];
    }
    __syncthreads();

    if (tid < 32) {
        const float v1 = s_y[tid];
        const float v2 = s_y[tid + 32];
        float s  = v1 + v2;
        float sq = v1 * v1 + v2 * v2;
        #pragma unroll
        for (int m = 16; m > 0; m >>= 1) {
            s  += __shfl_xor_sync(0xFFFFFFFFu, s,  m);
            sq += __shfl_xor_sync(0xFFFFFFFFu, sq, m);
        }
        if (tid == 0) {
            const float mean = s / 64.f;
            const float var  = sq / 64.f - mean * mean;
            s_stats[0] = mean;
            s_stats[1] = rsqrtf(var + 1e-3f);
        }
    }
    __syncthreads();

    if (tid < PLANES) {
        const float mean = s_stats[0], rstd = s_stats[1];
        float v = (s_y[tid] - mean) * rstd * gamma[tid] + beta[tid];
        s_y[tid] = fmaxf(v, 0.f);
    }
    __syncthreads();

    {
        const int c = tid;
        float acc = b2[c];
        #pragma unroll 8
        for (int p = 0; p < PLANES; p++)
            acc = fmaf(s_y[p], w2[p * C + c], acc);
        g_term[(size_t)b * C + c] = acc;
    }
}

// ---------------------------------------------------------------------------
// Kernel 3: out = x + term[b][c].
// 8 float4 per thread, ALL loads front-batched, no bounds predicates
// (n4 is an exact multiple of ADD_TPB*ADD_VPT for these shapes).
// __launch_bounds__(256,2) -> 128-reg budget so the 8 loads truly coexist
// (the previous 64-reg cap forced ptxas to serialize them).
// ---------------------------------------------------------------------------
#define ADD_VPT 8
#define ADD_TPB 256
__global__ __launch_bounds__(ADD_TPB, 2) void gc_add_kernel(
    const float4* __restrict__ x4, float4* __restrict__ out4)
{
    const size_t base = (size_t)blockIdx.x * (ADD_TPB * ADD_VPT) + threadIdx.x;

    float4 v[ADD_VPT];
    #pragma unroll
    for (int k = 0; k < ADD_VPT; k++)
        v[k] = __ldcs(x4 + base + (size_t)k * ADD_TPB);

    #pragma unroll
    for (int k = 0; k < ADD_VPT; k++) {
        const size_t i = base + (size_t)k * ADD_TPB;
        const int c4 = (int)(i & (C4 - 1));
        const int b  = (int)(i >> 18);                 // HW*C/4 = 2^18 per batch
        const float4 t = reinterpret_cast<const float4*>(g_term)[b * C4 + c4];
        v[k].x += t.x; v[k].y += t.y; v[k].z += t.z; v[k].w += t.w;
        __stcs(out4 + i, v[k]);
    }
}

extern "C" void kernel_launch(void* const* d_in, const int* in_sizes, int n_in,
                              void* d_out, int out_size)
{
    const float* x     = (const float*)d_in[0];
    const float* wm    = (const float*)d_in[1];
    const float* bm    = (const float*)d_in[2];
    const float* w1    = (const float*)d_in[3];
    const float* b1    = (const float*)d_in[4];
    const float* gamma = (const float*)d_in[5];
    const float* beta  = (const float*)d_in[6];
    const float* w2    = (const float*)d_in[7];
    const float* b2    = (const float*)d_in[8];
    float* out = (float*)d_out;

    const int B = in_sizes[0] / (HW * C);

    gc_pool_kernel<<<B * NCHUNK, 256>>>(x, wm, bm);
    gc_mlp_kernel<<<B, 256>>>(w1, b1, gamma, beta, w2, b2);

    const int n4 = out_size / 4;                 // 8,388,608 = 4096 * 2048
    const int elems_per_blk = ADD_TPB * ADD_VPT; // 2048
    gc_add_kernel<<<n4 / elems_per_blk, ADD_TPB>>>(
        (const float4*)x, (float4*)out);
}

// round 8
// speedup vs baseline: 1.0919x; 1.0384x over previous
#include <cuda_runtime.h>
#include <cuda_bf16.h>

// GlobalContextBlock (GCNet) — 2-kernel implementation.
// Shapes fixed: B=32, H=W=64 (HW=4096), C=256, HEADS=8, c1=32, planes=64.
//
// k1: one streaming pass over x computing softmax-pooling partials
//     (exp w/o max-subtraction: |logit| < ~7, fp32-safe), PLUS the bottleneck
//     MLP fused via the last-block-per-batch pattern (threadfence + atomic):
//     the last pool block of each batch reduces the partials -> ctx ->
//     MLP(256->64, LN eps=1e-3, ReLU, 64->256) -> g_term, hidden under the
//     other batches' pool streaming.
// k2: out = x + term[b][c]  (streaming, 8x float4/thread, no predicates)

#define HW    4096
#define C     256
#define C4    64
#define HEADS 8
#define PLANES 64
#define NCHUNK 32                      // spatial chunks per batch in k1
#define POS_PER_CHUNK (HW / NCHUNK)    // 128
#define MAXB  64

__device__ float    g_pnum[MAXB * NCHUNK * C];
__device__ float    g_pden[MAXB * NCHUNK * HEADS];
__device__ float    g_term[MAXB * C];
__device__ unsigned g_bar[MAXB];       // per-batch arrival counters (self-reset)

// ---------------------------------------------------------------------------
// Kernel 1: pooling partials + fused last-block MLP.
// grid = B*NCHUNK, 256 threads (8 warps). Warp w: half=w&1 -> 128 channels;
// positions s0 + (w>>1) + 4k. Lane l owns channels half*128+4l..4l+3.
// UB=8 positions batched; __launch_bounds__(256,3) keeps loads in flight.
// ---------------------------------------------------------------------------
#define UB 8
__global__ __launch_bounds__(256, 3) void gc_pool_mlp_kernel(
    const float* __restrict__ x, const float* __restrict__ wm,
    const float* __restrict__ bmp,
    const float* __restrict__ w1, const float* __restrict__ b1,
    const float* __restrict__ gamma, const float* __restrict__ beta,
    const float* __restrict__ w2, const float* __restrict__ b2)
{
    const int blk   = blockIdx.x;
    const int b     = blk / NCHUNK;
    const int chunk = blk % NCHUNK;
    const int s0    = chunk * POS_PER_CHUNK;

    const int tid  = threadIdx.x;
    const int w    = tid >> 5;
    const int l    = tid & 31;
    const int half = w & 1;
    const int wrow = w >> 1;            // 0..3

    const float4 wmv = *reinterpret_cast<const float4*>(wm + 4 * (l & 7));
    const float  bm  = bmp[0];

    const float* base = x + ((size_t)b * HW + s0 + wrow) * C + half * 128 + 4 * l;

    float4 acc = make_float4(0.f, 0.f, 0.f, 0.f);
    float  den = 0.f;

    #pragma unroll
    for (int kk = 0; kk < POS_PER_CHUNK / 4 / UB; kk++) {
        float4 xv[UB];
        #pragma unroll
        for (int u = 0; u < UB; u++)
            xv[u] = *reinterpret_cast<const float4*>(
                base + (size_t)(kk * UB + u) * 4 * C);

        float p[UB];
        #pragma unroll
        for (int u = 0; u < UB; u++)
            p[u] = xv[u].x * wmv.x + xv[u].y * wmv.y +
                   xv[u].z * wmv.z + xv[u].w * wmv.w;

        #pragma unroll
        for (int u = 0; u < UB; u++) p[u] += __shfl_xor_sync(0xFFFFFFFFu, p[u], 1);
        #pragma unroll
        for (int u = 0; u < UB; u++) p[u] += __shfl_xor_sync(0xFFFFFFFFu, p[u], 2);
        #pragma unroll
        for (int u = 0; u < UB; u++) p[u] += __shfl_xor_sync(0xFFFFFFFFu, p[u], 4);

        float e[UB];
        #pragma unroll
        for (int u = 0; u < UB; u++) e[u] = __expf(p[u] + bm);

        #pragma unroll
        for (int u = 0; u < UB; u++) {
            acc.x = fmaf(e[u], xv[u].x, acc.x);
            acc.y = fmaf(e[u], xv[u].y, acc.y);
            acc.z = fmaf(e[u], xv[u].z, acc.z);
            acc.w = fmaf(e[u], xv[u].w, acc.w);
            den  += e[u];
        }
    }

    __shared__ float s_num[8][128];
    __shared__ float s_den[8][4];
    s_num[w][4 * l + 0] = acc.x;
    s_num[w][4 * l + 1] = acc.y;
    s_num[w][4 * l + 2] = acc.z;
    s_num[w][4 * l + 3] = acc.w;
    if ((l & 7) == 0) s_den[w][l >> 3] = den;
    __syncthreads();

    {
        const int ch = tid;            // 0..255
        const int hf = ch >> 7;
        const int cl = ch & 127;
        g_pnum[(size_t)blk * C + ch] =
            s_num[hf][cl] + s_num[hf + 2][cl] + s_num[hf + 4][cl] + s_num[hf + 6][cl];
    }
    if (tid < HEADS) {
        const int hf = tid >> 2;
        const int hh = tid & 3;
        g_pden[(size_t)blk * HEADS + tid] =
            s_den[hf][hh] + s_den[hf + 2][hh] + s_den[hf + 4][hh] + s_den[hf + 6][hh];
    }

    // ---- last-block-per-batch detection (threadFenceReduction pattern) ----
    __shared__ int s_last;
    __threadfence();                   // publish this block's partials
    __syncthreads();
    if (tid == 0) {
        const unsigned old = atomicAdd(&g_bar[b], 1u);
        s_last = (old == NCHUNK - 1u);
        if (s_last) g_bar[b] = 0u;     // self-reset for next graph replay
    }
    __syncthreads();
    if (!s_last) return;
    __threadfence();                   // acquire: see all 32 blocks' partials

    // =====================  fused MLP for batch b  ==========================
    __shared__ float s_ctx[C];
    __shared__ float s_y[PLANES];
    __shared__ float s_stats[2];

    {
        const int c = tid;
        const int head = c >> 5;
        float num = 0.f, dn = 0.f;
        #pragma unroll
        for (int ch = 0; ch < NCHUNK; ch++) {
            num += g_pnum[((size_t)b * NCHUNK + ch) * C + c];
            dn  += g_pden[((size_t)b * NCHUNK + ch) * HEADS + head];
        }
        s_ctx[c] = num / dn;
    }
    __syncthreads();

    {
        const int p = tid >> 2;
        const int q = tid & 3;
        float a2 = 0.f;
        #pragma unroll 8
        for (int i = 0; i < 64; i++) {
            const int c = q * 64 + i;
            a2 = fmaf(s_ctx[c], w1[c * PLANES + p], a2);
        }
        a2 += __shfl_xor_sync(0xFFFFFFFFu, a2, 1);
        a2 += __shfl_xor_sync(0xFFFFFFFFu, a2, 2);
        if (q == 0) s_y[p] = a2 + b1[p];
    }
    __syncthreads();

    if (tid < 32) {
        const float v1 = s_y[tid];
        const float v2 = s_y[tid + 32];
        float s  = v1 + v2;
        float sq = v1 * v1 + v2 * v2;
        #pragma unroll
        for (int m = 16; m > 0; m >>= 1) {
            s  += __shfl_xor_sync(0xFFFFFFFFu, s,  m);
            sq += __shfl_xor_sync(0xFFFFFFFFu, sq, m);
        }
        if (tid == 0) {
            const float mean = s / 64.f;
            const float var  = sq / 64.f - mean * mean;
            s_stats[0] = mean;
            s_stats[1] = rsqrtf(var + 1e-3f);
        }
    }
    __syncthreads();

    if (tid < PLANES) {
        const float v = (s_y[tid] - s_stats[0]) * s_stats[1] * gamma[tid] + beta[tid];
        s_y[tid] = fmaxf(v, 0.f);
    }
    __syncthreads();

    {
        const int c = tid;
        float a3 = b2[c];
        #pragma unroll 8
        for (int p = 0; p < PLANES; p++)
            a3 = fmaf(s_y[p], w2[p * C + c], a3);
        g_term[(size_t)b * C + c] = a3;
    }
}

// ---------------------------------------------------------------------------
// Kernel 2: out = x + term[b][c].
// 8 float4 per thread, all loads front-batched, no bounds predicates
// (n4 = 8,388,608 is an exact multiple of 2048). 128-reg budget.
// ---------------------------------------------------------------------------
#define ADD_VPT 8
#define ADD_TPB 256
__global__ __launch_bounds__(ADD_TPB, 2) void gc_add_kernel(
    const float4* __restrict__ x4, float4* __restrict__ out4)
{
    const size_t base = (size_t)blockIdx.x * (ADD_TPB * ADD_VPT) + threadIdx.x;

    float4 v[ADD_VPT];
    #pragma unroll
    for (int k = 0; k < ADD_VPT; k++)
        v[k] = __ldcs(x4 + base + (size_t)k * ADD_TPB);

    #pragma unroll
    for (int k = 0; k < ADD_VPT; k++) {
        const size_t i = base + (size_t)k * ADD_TPB;
        const int c4 = (int)(i & (C4 - 1));
        const int b  = (int)(i >> 18);                 // HW*C/4 = 2^18 per batch
        const float4 t = reinterpret_cast<const float4*>(g_term)[b * C4 + c4];
        v[k].x += t.x; v[k].y += t.y; v[k].z += t.z; v[k].w += t.w;
        __stcs(out4 + i, v[k]);
    }
}

extern "C" void kernel_launch(void* const* d_in, const int* in_sizes, int n_in,
                              void* d_out, int out_size)
{
    const float* x     = (const float*)d_in[0];
    const float* wm    = (const float*)d_in[1];
    const float* bm    = (const float*)d_in[2];
    const float* w1    = (const float*)d_in[3];
    const float* b1    = (const float*)d_in[4];
    const float* gamma = (const float*)d_in[5];
    const float* beta  = (const float*)d_in[6];
    const float* w2    = (const float*)d_in[7];
    const float* b2    = (const float*)d_in[8];
    float* out = (float*)d_out;

    const int B = in_sizes[0] / (HW * C);

    gc_pool_mlp_kernel<<<B * NCHUNK, 256>>>(x, wm, bm, w1, b1, gamma, beta, w2, b2);

    const int n4 = out_size / 4;                 // 8,388,608 = 4096 * 2048
    const int elems_per_blk = ADD_TPB * ADD_VPT; // 2048
    gc_add_kernel<<<n4 / elems_per_blk, ADD_TPB>>>(
        (const float4*)x, (float4*)out);
}